// round 12
// baseline (speedup 1.0000x reference)
#include <cuda_runtime.h>
#include <cuda_bf16.h>
#include <cstdint>

// Problem constants (fixed by the dataset): N=50000, E=800000, D=128.
#define D 128
#define MAXN 65536
#define MAXE 1048576
#define SCAN_B 1024
#define MAXBLK 64

__device__ int   g_deg[MAXN];
__device__ float g_dinv[MAXN];
__device__ int   g_rowStart[MAXN + 1];
__device__ int   g_cursor[MAXN];
__device__ int   g_csr_src[MAXE];
__device__ float g_csr_w[MAXE];
__device__ int   g_blockSums[MAXBLK];

// Packed dual-FMA: acc.{lo,hi} += a.{lo,hi} * b.{lo,hi}   (2 fp32 FMAs, 1 instr)
#define FFMA2(acc, a, b) \
    asm("fma.rn.f32x2 %0, %1, %2, %0;" : "+l"(acc) : "l"(a), "l"(b))

// ---------------------------------------------------------------------------
// K1: deg[i] = 1 (self-loop)
// ---------------------------------------------------------------------------
__global__ void k_deg_init(int N) {
    int i = blockIdx.x * blockDim.x + threadIdx.x;
    if (i < N) g_deg[i] = 1;
}

// ---------------------------------------------------------------------------
// K2: deg[dst[e]] += 1
// ---------------------------------------------------------------------------
__global__ void k_deg_count(const int* __restrict__ adj, int E) {
    int e = blockIdx.x * blockDim.x + threadIdx.x;
    if (e < E) atomicAdd(&g_deg[adj[E + e]], 1);
}

// ---------------------------------------------------------------------------
// K3a: per-block exclusive scan of (deg-1); dinv fused.
// ---------------------------------------------------------------------------
__global__ void __launch_bounds__(SCAN_B) k_scan_partial(int N) {
    __shared__ int wsum[32];
    int tid = threadIdx.x, lane = tid & 31, wid = tid >> 5;
    int i = blockIdx.x * SCAN_B + tid;
    int deg = (i < N) ? g_deg[i] : 1;
    if (i < N) g_dinv[i] = rsqrtf((float)deg);
    int v = deg - 1;
    int inc = v;
    #pragma unroll
    for (int o = 1; o < 32; o <<= 1) {
        int t = __shfl_up_sync(0xFFFFFFFFu, inc, o);
        if (lane >= o) inc += t;
    }
    if (lane == 31) wsum[wid] = inc;
    __syncthreads();
    if (wid == 0) {
        int w = wsum[lane];
        int winc = w;
        #pragma unroll
        for (int o = 1; o < 32; o <<= 1) {
            int t = __shfl_up_sync(0xFFFFFFFFu, winc, o);
            if (lane >= o) winc += t;
        }
        wsum[lane] = winc - w;
        if (lane == 31) g_blockSums[blockIdx.x] = winc;
    }
    __syncthreads();
    if (i < N) g_rowStart[i] = wsum[wid] + (inc - v);
}

// ---------------------------------------------------------------------------
// K3b: exclusive scan of block sums — single warp, shuffle scan (nb <= 64).
// ---------------------------------------------------------------------------
__global__ void k_scan_mid(int nb) {
    int lane = threadIdx.x;
    int a = (lane < nb) ? g_blockSums[lane] : 0;
    int b = (lane + 32 < nb) ? g_blockSums[lane + 32] : 0;
    int ia = a, ib = b;
    #pragma unroll
    for (int o = 1; o < 32; o <<= 1) {
        int t = __shfl_up_sync(0xFFFFFFFFu, ia, o);
        if (lane >= o) ia += t;
        int u = __shfl_up_sync(0xFFFFFFFFu, ib, o);
        if (lane >= o) ib += u;
    }
    int totA = __shfl_sync(0xFFFFFFFFu, ia, 31);
    if (lane < nb)      g_blockSums[lane]      = ia - a;
    if (lane + 32 < nb) g_blockSums[lane + 32] = ib - b + totA;
}

// ---------------------------------------------------------------------------
// K3c: add block offsets; write rowStart + cursor; rowStart[N] = E.
// ---------------------------------------------------------------------------
__global__ void __launch_bounds__(SCAN_B) k_scan_add(int N, int E) {
    int i = blockIdx.x * SCAN_B + threadIdx.x;
    if (i < N) {
        int val = g_rowStart[i] + g_blockSums[blockIdx.x];
        g_rowStart[i] = val;
        g_cursor[i]   = val;
    }
    if (i == 0) g_rowStart[N] = E;
}

// ---------------------------------------------------------------------------
// K5: fill CSR
// ---------------------------------------------------------------------------
__global__ void k_fill(const int* __restrict__ adj, int E) {
    int e = blockIdx.x * blockDim.x + threadIdx.x;
    if (e >= E) return;
    int s = __ldg(&adj[e]);
    int t = __ldg(&adj[E + e]);
    float w = g_dinv[s] * g_dinv[t];
    int pos = atomicAdd(&g_cursor[t], 1);
    g_csr_src[pos] = s;
    g_csr_w[pos]   = w;
}

// ---------------------------------------------------------------------------
// K6: aggregation by gather — one warp per node.
// ---------------------------------------------------------------------------
__global__ void __launch_bounds__(256) k_agg(const float4* __restrict__ x4,
                                             float4* __restrict__ out4, int N) {
    int gt   = blockIdx.x * blockDim.x + threadIdx.x;
    int node = gt >> 5;
    int lane = gt & 31;
    if (node >= N) return;

    float dv = g_dinv[node];
    float4 v = x4[node * 32 + lane];
    float w0 = dv * dv;
    float4 acc0 = make_float4(v.x * w0, v.y * w0, v.z * w0, v.w * w0);
    float4 acc1 = make_float4(0.f, 0.f, 0.f, 0.f);

    int beg = g_rowStart[node];
    int end = g_rowStart[node + 1];

    int i = beg;
    for (; i + 1 < end; i += 2) {
        int   s0 = g_csr_src[i];
        int   s1 = g_csr_src[i + 1];
        float w0e = g_csr_w[i];
        float w1e = g_csr_w[i + 1];
        float4 a = x4[s0 * 32 + lane];
        float4 b = x4[s1 * 32 + lane];
        acc0.x = fmaf(w0e, a.x, acc0.x); acc0.y = fmaf(w0e, a.y, acc0.y);
        acc0.z = fmaf(w0e, a.z, acc0.z); acc0.w = fmaf(w0e, a.w, acc0.w);
        acc1.x = fmaf(w1e, b.x, acc1.x); acc1.y = fmaf(w1e, b.y, acc1.y);
        acc1.z = fmaf(w1e, b.z, acc1.z); acc1.w = fmaf(w1e, b.w, acc1.w);
    }
    if (i < end) {
        int   s0 = g_csr_src[i];
        float we = g_csr_w[i];
        float4 a = x4[s0 * 32 + lane];
        acc0.x = fmaf(we, a.x, acc0.x); acc0.y = fmaf(we, a.y, acc0.y);
        acc0.z = fmaf(we, a.z, acc0.z); acc0.w = fmaf(we, a.w, acc0.w);
    }
    acc0.x += acc1.x; acc0.y += acc1.y; acc0.z += acc1.z; acc0.w += acc1.w;
    out4[node * 32 + lane] = acc0;
}

// ---------------------------------------------------------------------------
// K7: fused GEMM (K=256: [aggx | x] @ [Wg ; Wl]) + bias + eps + LayerNorm,
//     mainloop in packed fma.rn.f32x2 (2 fp32 FMAs / instr).
//
// Block: 256 threads, tile = 64 rows x 128 cols; thread = 8 rows x 4 cols.
// K-pairing: acc lo-half accumulates even k, hi-half odd k; added at the end.
// A staged DUPLICATED in smem: As2[r][k] holds (a,a) as one 8-byte word, so
// ld.shared.v4 yields the two 64-bit dup operands for k and k+1 directly.
// Dynamic smem: Ws 64x128 f32 (32KB) + As2 64x64 8B (32KB) = 64KB.
// ---------------------------------------------------------------------------
#define BM 64
#define KC 64
#define GEMM_SMEM (32768 + 32768)

__global__ void __launch_bounds__(256)
k_gemm_ln(const float* __restrict__ x,
          const float* __restrict__ Wg,
          const float* __restrict__ Wl,
          const float* __restrict__ bias,
          const float* __restrict__ lnw,
          const float* __restrict__ lnb,
          float* __restrict__ out, int N) {
    extern __shared__ char sm[];
    float (*Ws)[D] = (float(*)[D])sm;                                  // [KC][128]
    unsigned long long (*As2)[KC] = (unsigned long long(*)[KC])(sm + 32768); // [BM][KC] dup pairs

    int tid  = threadIdx.x;
    int tx   = tid & 31;
    int ty   = tid >> 5;
    int row0 = blockIdx.x * BM;

    unsigned long long acc[8][2];
    #pragma unroll
    for (int rr = 0; rr < 8; rr++) { acc[rr][0] = 0ull; acc[rr][1] = 0ull; }

    #pragma unroll 1
    for (int kc = 0; kc < 4; kc++) {
        int k0 = kc * KC;
        __syncthreads();
        // ---- stage W chunk: rows k0..k0+63 of [Wg ; Wl] ----
        for (int i = tid; i < KC * (D / 4); i += 256) {
            int kk = i >> 5;
            int c4 = i & 31;
            int kglob = k0 + kk;
            const float* wsrc = (kglob < D) ? (Wg + kglob * D)
                                            : (Wl + (kglob - D) * D);
            ((float4*)&Ws[kk][0])[c4] = ((const float4*)wsrc)[c4];
        }
        // ---- stage A chunk duplicated: As2[r][k] = (a,a) ----
        {
            const float* Asrc = (kc < 2) ? out : x;   // k<128 -> aggx (in out)
            int kofs = (kc & 1) * KC;
            for (int i = tid; i < BM * (KC / 4); i += 256) {
                int r   = i >> 4;          // 0..63
                int c4  = i & 15;          // float4 index (4 k values)
                int row = row0 + r;
                float4 v = make_float4(0.f, 0.f, 0.f, 0.f);
                if (row < N)
                    v = *(const float4*)(Asrc + (size_t)row * D + kofs + c4 * 4);
                uint4 p0 = make_uint4(__float_as_uint(v.x), __float_as_uint(v.x),
                                      __float_as_uint(v.y), __float_as_uint(v.y));
                uint4 p1 = make_uint4(__float_as_uint(v.z), __float_as_uint(v.z),
                                      __float_as_uint(v.w), __float_as_uint(v.w));
                uint4* dst = (uint4*)&As2[r][0];
                dst[2 * c4]     = p0;
                dst[2 * c4 + 1] = p1;
            }
        }
        __syncthreads();

        // ---- mainloop: 2 k per iter, packed FFMA2 ----
        #pragma unroll
        for (int k = 0; k < KC; k += 2) {
            ulonglong2 w0 = *(const ulonglong2*)&Ws[k][tx * 4];     // k:   (c0,c1),(c2,c3)
            ulonglong2 w1 = *(const ulonglong2*)&Ws[k + 1][tx * 4]; // k+1: (c0,c1),(c2,c3)
            #pragma unroll
            for (int rr = 0; rr < 8; rr++) {
                ulonglong2 av = *(const ulonglong2*)&As2[ty * 8 + rr][k];
                // av.x = (a_k, a_k), av.y = (a_{k+1}, a_{k+1})
                FFMA2(acc[rr][0], av.x, w0.x);
                FFMA2(acc[rr][1], av.x, w0.y);
                FFMA2(acc[rr][0], av.y, w1.x);
                FFMA2(acc[rr][1], av.y, w1.y);
            }
        }
    }

    // ---- epilogue: unpack, bias + eps, LayerNorm per row ----
    float4 bv  = ((const float4*)bias)[tx];
    float4 lwv = ((const float4*)lnw)[tx];
    float4 lbv = ((const float4*)lnb)[tx];

    #pragma unroll
    for (int rr = 0; rr < 8; rr++) {
        int row = row0 + ty * 8 + rr;
        float c0 = __uint_as_float((uint32_t)acc[rr][0])
                 + __uint_as_float((uint32_t)(acc[rr][0] >> 32)) + bv.x + 1e-6f;
        float c1 = __uint_as_float((uint32_t)(acc[rr][0] & 0xFFFFFFFFull)) * 0.f; // placeholder
        // NOTE: acc[rr][0] holds packed (col0, col1); acc[rr][1] holds (col2, col3).
        // lo-half = even-k partial, hi-half = odd-k partial? No — halves ARE the
        // two columns; even/odd k both accumulated into the same half via av dup.
        (void)c1;
        float col0 = __uint_as_float((uint32_t)acc[rr][0]);
        float col1 = __uint_as_float((uint32_t)(acc[rr][0] >> 32));
        float col2 = __uint_as_float((uint32_t)acc[rr][1]);
        float col3 = __uint_as_float((uint32_t)(acc[rr][1] >> 32));
        col0 = col0 + bv.x + 1e-6f;
        col1 = col1 + bv.y + 1e-6f;
        col2 = col2 + bv.z + 1e-6f;
        col3 = col3 + bv.w + 1e-6f;
        // (c0 above was scratch; recomputed cleanly here)
        float s  = col0 + col1 + col2 + col3;
        float s2 = col0 * col0 + col1 * col1 + col2 * col2 + col3 * col3;
        #pragma unroll
        for (int off = 16; off > 0; off >>= 1) {
            s  += __shfl_xor_sync(0xFFFFFFFFu, s,  off);
            s2 += __shfl_xor_sync(0xFFFFFFFFu, s2, off);
        }
        float mu   = s * (1.0f / D);
        float var  = fmaxf(s2 * (1.0f / D) - mu * mu, 0.0f);
        float rstd = rsqrtf(var + 1e-5f);
        if (row < N) {
            float4 o;
            o.x = (col0 - mu) * rstd * lwv.x + lbv.x;
            o.y = (col1 - mu) * rstd * lwv.y + lbv.y;
            o.z = (col2 - mu) * rstd * lwv.z + lbv.z;
            o.w = (col3 - mu) * rstd * lwv.w + lbv.w;
            ((float4*)(out + (size_t)row * D))[tx] = o;
        }
    }
}

// ---------------------------------------------------------------------------
extern "C" void kernel_launch(void* const* d_in, const int* in_sizes, int n_in,
                              void* d_out, int out_size) {
    const int*   adj = (const int*)d_in[0];
    const float* x   = (const float*)d_in[1];
    const float* Wg  = (const float*)d_in[2];
    const float* bg  = (const float*)d_in[3];
    const float* Wl  = (const float*)d_in[4];
    const float* lnw = (const float*)d_in[5];
    const float* lnb = (const float*)d_in[6];
    float*       out = (float*)d_out;

    int E = in_sizes[0] / 2;
    int N = in_sizes[1] / D;
    int nb = (N + SCAN_B - 1) / SCAN_B;

    cudaFuncSetAttribute(k_gemm_ln, cudaFuncAttributeMaxDynamicSharedMemorySize,
                         GEMM_SMEM);

    k_deg_init<<<(N + 255) / 256, 256>>>(N);
    k_deg_count<<<(E + 255) / 256, 256>>>(adj, E);
    k_scan_partial<<<nb, SCAN_B>>>(N);
    k_scan_mid<<<1, 32>>>(nb);
    k_scan_add<<<nb, SCAN_B>>>(N, E);
    k_fill<<<(E + 255) / 256, 256>>>(adj, E);

    int aggThreads = N * 32;
    k_agg<<<(aggThreads + 255) / 256, 256>>>((const float4*)x, (float4*)out, N);

    int gemmBlocks = (N + BM - 1) / BM;
    k_gemm_ln<<<gemmBlocks, 256, GEMM_SMEM>>>(x, Wg, Wl, bg, lnw, lnb, out, N);
}

// round 13
// speedup vs baseline: 1.0513x; 1.0513x over previous
#include <cuda_runtime.h>
#include <cuda_bf16.h>
#include <cstdint>

// Problem constants (fixed by the dataset): N=50000, E=800000, D=128.
#define D 128
#define MAXN 65536
#define MAXE 1048576
#define SCAN_B 1024
#define MAXBLK 64

__device__ int   g_deg[MAXN];
__device__ float g_dinv[MAXN];
__device__ int   g_rowStart[MAXN + 1];
__device__ int   g_cursor[MAXN];
__device__ int2  g_csr[MAXE];          // (src, float_as_int(w))
__device__ int   g_blockSums[MAXBLK];
__device__ float g_Wt[128 * 256];      // W^T: [n][k], W = [Wg ; Wl]

// Packed dual-FMA: acc.{lo,hi} += a.{lo,hi} * b.{lo,hi}   (2 fp32 FMAs, 1 instr)
#define FFMA2(acc, a, b) \
    asm("fma.rn.f32x2 %0, %1, %2, %0;" : "+l"(acc) : "l"(a), "l"(b))

__device__ __forceinline__ float lo32(unsigned long long v) {
    return __uint_as_float((uint32_t)v);
}
__device__ __forceinline__ float hi32(unsigned long long v) {
    return __uint_as_float((uint32_t)(v >> 32));
}

// ---------------------------------------------------------------------------
// K1: deg[i] = 1 (self-loop)
// ---------------------------------------------------------------------------
__global__ void k_deg_init(int N) {
    int i = blockIdx.x * blockDim.x + threadIdx.x;
    if (i < N) g_deg[i] = 1;
}

// ---------------------------------------------------------------------------
// K2: deg[dst[e]] += 1
// ---------------------------------------------------------------------------
__global__ void k_deg_count(const int* __restrict__ adj, int E) {
    int e = blockIdx.x * blockDim.x + threadIdx.x;
    if (e < E) atomicAdd(&g_deg[adj[E + e]], 1);
}

// ---------------------------------------------------------------------------
// Kw: build W^T = [Wg ; Wl]^T as g_Wt[n][k]  (32K elements, one-time)
// ---------------------------------------------------------------------------
__global__ void k_wt(const float* __restrict__ Wg, const float* __restrict__ Wl) {
    int i = blockIdx.x * blockDim.x + threadIdx.x;
    if (i >= 128 * 256) return;
    int k = i >> 7;
    int n = i & 127;
    float v = (k < 128) ? Wg[k * 128 + n] : Wl[(k - 128) * 128 + n];
    g_Wt[n * 256 + k] = v;
}

// ---------------------------------------------------------------------------
// K3a: per-block exclusive scan of (deg-1); dinv fused.
// ---------------------------------------------------------------------------
__global__ void __launch_bounds__(SCAN_B) k_scan_partial(int N) {
    __shared__ int wsum[32];
    int tid = threadIdx.x, lane = tid & 31, wid = tid >> 5;
    int i = blockIdx.x * SCAN_B + tid;
    int deg = (i < N) ? g_deg[i] : 1;
    if (i < N) g_dinv[i] = rsqrtf((float)deg);
    int v = deg - 1;
    int inc = v;
    #pragma unroll
    for (int o = 1; o < 32; o <<= 1) {
        int t = __shfl_up_sync(0xFFFFFFFFu, inc, o);
        if (lane >= o) inc += t;
    }
    if (lane == 31) wsum[wid] = inc;
    __syncthreads();
    if (wid == 0) {
        int w = wsum[lane];
        int winc = w;
        #pragma unroll
        for (int o = 1; o < 32; o <<= 1) {
            int t = __shfl_up_sync(0xFFFFFFFFu, winc, o);
            if (lane >= o) winc += t;
        }
        wsum[lane] = winc - w;
        if (lane == 31) g_blockSums[blockIdx.x] = winc;
    }
    __syncthreads();
    if (i < N) g_rowStart[i] = wsum[wid] + (inc - v);
}

// ---------------------------------------------------------------------------
// K3b: exclusive scan of block sums — single warp, shuffle scan (nb <= 64).
// ---------------------------------------------------------------------------
__global__ void k_scan_mid(int nb) {
    int lane = threadIdx.x;
    int a = (lane < nb) ? g_blockSums[lane] : 0;
    int b = (lane + 32 < nb) ? g_blockSums[lane + 32] : 0;
    int ia = a, ib = b;
    #pragma unroll
    for (int o = 1; o < 32; o <<= 1) {
        int t = __shfl_up_sync(0xFFFFFFFFu, ia, o);
        if (lane >= o) ia += t;
        int u = __shfl_up_sync(0xFFFFFFFFu, ib, o);
        if (lane >= o) ib += u;
    }
    int totA = __shfl_sync(0xFFFFFFFFu, ia, 31);
    if (lane < nb)      g_blockSums[lane]      = ia - a;
    if (lane + 32 < nb) g_blockSums[lane + 32] = ib - b + totA;
}

// ---------------------------------------------------------------------------
// K3c: add block offsets; write rowStart + cursor; rowStart[N] = E.
// ---------------------------------------------------------------------------
__global__ void __launch_bounds__(SCAN_B) k_scan_add(int N, int E) {
    int i = blockIdx.x * SCAN_B + threadIdx.x;
    if (i < N) {
        int val = g_rowStart[i] + g_blockSums[blockIdx.x];
        g_rowStart[i] = val;
        g_cursor[i]   = val;
    }
    if (i == 0) g_rowStart[N] = E;
}

// ---------------------------------------------------------------------------
// K5: fill CSR (combined (src, w) int2 -> single STG.64)
// ---------------------------------------------------------------------------
__global__ void k_fill(const int* __restrict__ adj, int E) {
    int e = blockIdx.x * blockDim.x + threadIdx.x;
    if (e >= E) return;
    int s = __ldg(&adj[e]);
    int t = __ldg(&adj[E + e]);
    float w = g_dinv[s] * g_dinv[t];
    int pos = atomicAdd(&g_cursor[t], 1);
    g_csr[pos] = make_int2(s, __float_as_int(w));
}

// ---------------------------------------------------------------------------
// K6: aggregation by gather — one warp per node.
// ---------------------------------------------------------------------------
__global__ void __launch_bounds__(256) k_agg(const float4* __restrict__ x4,
                                             float4* __restrict__ out4, int N) {
    int gt   = blockIdx.x * blockDim.x + threadIdx.x;
    int node = gt >> 5;
    int lane = gt & 31;
    if (node >= N) return;

    float dv = g_dinv[node];
    float4 v = x4[node * 32 + lane];
    float w0 = dv * dv;
    float4 acc0 = make_float4(v.x * w0, v.y * w0, v.z * w0, v.w * w0);
    float4 acc1 = make_float4(0.f, 0.f, 0.f, 0.f);

    int beg = g_rowStart[node];
    int end = g_rowStart[node + 1];

    int i = beg;
    for (; i + 1 < end; i += 2) {
        int2 e0 = g_csr[i];
        int2 e1 = g_csr[i + 1];
        float w0e = __int_as_float(e0.y);
        float w1e = __int_as_float(e1.y);
        float4 a = x4[e0.x * 32 + lane];
        float4 b = x4[e1.x * 32 + lane];
        acc0.x = fmaf(w0e, a.x, acc0.x); acc0.y = fmaf(w0e, a.y, acc0.y);
        acc0.z = fmaf(w0e, a.z, acc0.z); acc0.w = fmaf(w0e, a.w, acc0.w);
        acc1.x = fmaf(w1e, b.x, acc1.x); acc1.y = fmaf(w1e, b.y, acc1.y);
        acc1.z = fmaf(w1e, b.z, acc1.z); acc1.w = fmaf(w1e, b.w, acc1.w);
    }
    if (i < end) {
        int2 e0 = g_csr[i];
        float we = __int_as_float(e0.y);
        float4 a = x4[e0.x * 32 + lane];
        acc0.x = fmaf(we, a.x, acc0.x); acc0.y = fmaf(we, a.y, acc0.y);
        acc0.z = fmaf(we, a.z, acc0.z); acc0.w = fmaf(we, a.w, acc0.w);
    }
    acc0.x += acc1.x; acc0.y += acc1.y; acc0.z += acc1.z; acc0.w += acc1.w;
    out4[node * 32 + lane] = acc0;
}

// ---------------------------------------------------------------------------
// K7: fused GEMM (K=256: [aggx | x] @ Wt^T) + bias + eps + LayerNorm.
//     FFMA2 mainloop with K-pairing: acc lo = even-k sum, hi = odd-k sum.
//     A row-major smem -> (a_k,a_k+1) contiguous, LDS.128 broadcast.
//     W staged TRANSPOSED (Wt_s[col][k], XOR-swizzled) -> (w_k,w_k+1)
//     contiguous, LDS.128 lane-distinct across 8 bank groups.
//
// Block: 256 threads, tile = 64 rows x 128 cols; thread = 8 rows x 4 cols.
// Dynamic smem: Wt_s 128x64 f32 (32KB) + As 64x64 f32 (16KB) = 48KB.
// ---------------------------------------------------------------------------
#define BM 64
#define KC 64
#define GEMM_SMEM (32768 + 16384)

__global__ void __launch_bounds__(256, 2)
k_gemm_ln(const float* __restrict__ x,
          const float* __restrict__ bias,
          const float* __restrict__ lnw,
          const float* __restrict__ lnb,
          float* __restrict__ out, int N) {
    extern __shared__ char sm[];
    float (*Wt_s)[KC] = (float(*)[KC])sm;              // [128][64]
    float (*As)[KC]   = (float(*)[KC])(sm + 32768);    // [64][64]

    int tid  = threadIdx.x;
    int tx   = tid & 31;
    int ty   = tid >> 5;
    int row0 = blockIdx.x * BM;
    int sw   = tx & 7;

    unsigned long long acc[8][4];
    #pragma unroll
    for (int rr = 0; rr < 8; rr++)
        #pragma unroll
        for (int j = 0; j < 4; j++) acc[rr][j] = 0ull;

    #pragma unroll 1
    for (int kc = 0; kc < 4; kc++) {
        int k0 = kc * KC;
        __syncthreads();
        // ---- stage Wt chunk: 128 cols x 16 units of 4k, XOR-swizzled ----
        #pragma unroll
        for (int g = 0; g < 8; g++) {
            int i   = tid + g * 256;      // 0..2047
            int col = i >> 4;
            int u   = i & 15;
            float4 v = *(const float4*)(g_Wt + col * 256 + k0 + u * 4);
            int phys = u ^ ((col >> 2) & 7);
            *(float4*)&Wt_s[col][phys * 4] = v;
        }
        // ---- stage A chunk: 64 rows x 64 k (row-major, no swizzle) ----
        {
            const float* Asrc = (kc < 2) ? out : x;   // k<128 -> aggx (in out)
            int kofs = (kc & 1) * KC;
            #pragma unroll
            for (int g = 0; g < 4; g++) {
                int i  = tid + g * 256;   // 0..1023
                int r  = i >> 4;
                int u  = i & 15;
                int row = row0 + r;
                float4 v = make_float4(0.f, 0.f, 0.f, 0.f);
                if (row < N)
                    v = *(const float4*)(Asrc + (size_t)row * D + kofs + u * 4);
                *(float4*)&As[r][u * 4] = v;
            }
        }
        __syncthreads();

        // ---- mainloop: 4 k per unit, packed FFMA2 ----
        #pragma unroll 4
        for (int u = 0; u < 16; u++) {
            int pu = (u ^ sw) * 4;
            ulonglong2 wv0 = *(const ulonglong2*)&Wt_s[tx * 4 + 0][pu];
            ulonglong2 wv1 = *(const ulonglong2*)&Wt_s[tx * 4 + 1][pu];
            ulonglong2 wv2 = *(const ulonglong2*)&Wt_s[tx * 4 + 2][pu];
            ulonglong2 wv3 = *(const ulonglong2*)&Wt_s[tx * 4 + 3][pu];
            #pragma unroll
            for (int rr = 0; rr < 8; rr++) {
                ulonglong2 av = *(const ulonglong2*)&As[ty * 8 + rr][u * 4];
                FFMA2(acc[rr][0], av.x, wv0.x); FFMA2(acc[rr][0], av.y, wv0.y);
                FFMA2(acc[rr][1], av.x, wv1.x); FFMA2(acc[rr][1], av.y, wv1.y);
                FFMA2(acc[rr][2], av.x, wv2.x); FFMA2(acc[rr][2], av.y, wv2.y);
                FFMA2(acc[rr][3], av.x, wv3.x); FFMA2(acc[rr][3], av.y, wv3.y);
            }
        }
    }

    // ---- epilogue: unpack (lo=even-k, hi=odd-k), bias+eps, LayerNorm ----
    float4 bv  = ((const float4*)bias)[tx];
    float4 lwv = ((const float4*)lnw)[tx];
    float4 lbv = ((const float4*)lnb)[tx];

    #pragma unroll
    for (int rr = 0; rr < 8; rr++) {
        int row = row0 + ty * 8 + rr;
        float c0 = lo32(acc[rr][0]) + hi32(acc[rr][0]) + bv.x + 1e-6f;
        float c1 = lo32(acc[rr][1]) + hi32(acc[rr][1]) + bv.y + 1e-6f;
        float c2 = lo32(acc[rr][2]) + hi32(acc[rr][2]) + bv.z + 1e-6f;
        float c3 = lo32(acc[rr][3]) + hi32(acc[rr][3]) + bv.w + 1e-6f;
        float s  = c0 + c1 + c2 + c3;
        float s2 = c0 * c0 + c1 * c1 + c2 * c2 + c3 * c3;
        #pragma unroll
        for (int off = 16; off > 0; off >>= 1) {
            s  += __shfl_xor_sync(0xFFFFFFFFu, s,  off);
            s2 += __shfl_xor_sync(0xFFFFFFFFu, s2, off);
        }
        float mu   = s * (1.0f / D);
        float var  = fmaxf(s2 * (1.0f / D) - mu * mu, 0.0f);
        float rstd = rsqrtf(var + 1e-5f);
        if (row < N) {
            float4 o;
            o.x = (c0 - mu) * rstd * lwv.x + lbv.x;
            o.y = (c1 - mu) * rstd * lwv.y + lbv.y;
            o.z = (c2 - mu) * rstd * lwv.z + lbv.z;
            o.w = (c3 - mu) * rstd * lwv.w + lbv.w;
            ((float4*)(out + (size_t)row * D))[tx] = o;
        }
    }
}

// ---------------------------------------------------------------------------
extern "C" void kernel_launch(void* const* d_in, const int* in_sizes, int n_in,
                              void* d_out, int out_size) {
    const int*   adj = (const int*)d_in[0];
    const float* x   = (const float*)d_in[1];
    const float* Wg  = (const float*)d_in[2];
    const float* bg  = (const float*)d_in[3];
    const float* Wl  = (const float*)d_in[4];
    const float* lnw = (const float*)d_in[5];
    const float* lnb = (const float*)d_in[6];
    float*       out = (float*)d_out;

    int E = in_sizes[0] / 2;
    int N = in_sizes[1] / D;
    int nb = (N + SCAN_B - 1) / SCAN_B;

    cudaFuncSetAttribute(k_gemm_ln, cudaFuncAttributeMaxDynamicSharedMemorySize,
                         GEMM_SMEM);

    k_deg_init<<<(N + 255) / 256, 256>>>(N);
    k_deg_count<<<(E + 255) / 256, 256>>>(adj, E);
    k_wt<<<(128 * 256 + 255) / 256, 256>>>(Wg, Wl);
    k_scan_partial<<<nb, SCAN_B>>>(N);
    k_scan_mid<<<1, 32>>>(nb);
    k_scan_add<<<nb, SCAN_B>>>(N, E);
    k_fill<<<(E + 255) / 256, 256>>>(adj, E);

    int aggThreads = N * 32;
    k_agg<<<(aggThreads + 255) / 256, 256>>>((const float4*)x, (float4*)out, N);

    int gemmBlocks = (N + BM - 1) / BM;
    k_gemm_ln<<<gemmBlocks, 256, GEMM_SMEM>>>(x, bg, lnw, lnb, out, N);
}